// round 9
// baseline (speedup 1.0000x reference)
#include <cuda_runtime.h>
#include <cuda_fp8.h>
#include <cstdint>

// Problem constants
#define N_TOT   32768
#define D_DIM   256
#define K_CODES 1024
#define Q_ELEMS 8388608
#define GATHER_BLOCKS 2048
#define TAU     8e-3f

// smem geometry (bytes). 64-row CTA.
#define XPB     272                  // xs8 row pitch (bytes)
#define SO_XS   0                    // 64*272  = 17408
#define SO_ES0  17408                // 128*272 = 34816
#define SO_ES1  52224
#define SO_EN   87040                // 1024 floats
#define SO_NORM 91136                // 64 floats
#define SO_FLAG 91392                // cnt + 64 ints
#define SMEM_TOTAL 91712

// Device scratch
__device__ float    g_enorm[K_CODES];
__device__ uint8_t  g_e8[K_CODES * D_DIM];     // e4m3, scaled x512
__device__ int      g_idx[N_TOT];
__device__ float    g_partials[GATHER_BLOCKS];
__device__ int      g_hist[K_CODES];

__device__ __forceinline__ float warpReduceSum(float v) {
    #pragma unroll
    for (int o = 16; o > 0; o >>= 1) v += __shfl_down_sync(0xffffffffu, v, o);
    return v;
}
__device__ __forceinline__ uint32_t smem_u32(const void* p) {
    uint32_t a;
    asm("{ .reg .u64 t; cvta.to.shared.u64 t, %1; cvt.u32.u64 %0, t; }" : "=r"(a) : "l"(p));
    return a;
}
// 16-bit pack: high byte = fp8(hi), low byte = fp8(lo)
__device__ __forceinline__ uint16_t pack8x2(float hi, float lo) {
    uint16_t r;
    asm("cvt.rn.satfinite.e4m3x2.f32 %0, %1, %2;" : "=h"(r) : "f"(hi), "f"(lo));
    return r;
}

#define LDM_X4(r0,r1,r2,r3, a)                                                 \
    asm volatile("ldmatrix.sync.aligned.m8n8.x4.shared.b16 {%0,%1,%2,%3}, [%4];" \
                 : "=r"(r0), "=r"(r1), "=r"(r2), "=r"(r3) : "r"(a))
#define MMA_FP8(c0,c1,c2,c3, a0,a1,a2,a3, b0,b1)                               \
    asm volatile("mma.sync.aligned.m16n8k32.row.col.f32.e4m3.e4m3.f32 "        \
                 "{%0,%1,%2,%3},{%4,%5,%6,%7},{%8,%9},{%0,%1,%2,%3};"          \
                 : "+f"(c0), "+f"(c1), "+f"(c2), "+f"(c3)                      \
                 : "r"(a0), "r"(a1), "r"(a2), "r"(a3), "r"(b0), "r"(b1))
#define CP_ASYNC16(dst, src)                                                   \
    asm volatile("cp.async.cg.shared.global [%0], [%1], 16;" :: "r"(dst), "l"(src))
#define CP_COMMIT() asm volatile("cp.async.commit_group;" ::: "memory")
#define CP_WAIT(n)  asm volatile("cp.async.wait_group %0;" :: "n"(n) : "memory")

__device__ __forceinline__ void ins4(float v, int k, float bv[4], int bi[4]) {
    if (v < bv[3] || (v == bv[3] && k < bi[3])) {
        bv[3] = v; bi[3] = k;
        #pragma unroll
        for (int t = 3; t > 0; t--) {
            if (bv[t] < bv[t-1] || (bv[t] == bv[t-1] && bi[t] < bi[t-1])) {
                float tv = bv[t]; bv[t] = bv[t-1]; bv[t-1] = tv;
                int   ti = bi[t]; bi[t] = bi[t-1]; bi[t-1] = ti;
            }
        }
    }
}

// ---------------------------------------------------------------------------
// 1) ||e_k||^2 + e -> e4m3 (x512) + zero hist. grid=1024, block=256
// ---------------------------------------------------------------------------
__global__ void enorm_kernel(const float* __restrict__ emb) {
    __shared__ float red[8];
    int k = blockIdx.x;
    float v = emb[k * D_DIM + threadIdx.x];
    g_e8[k * D_DIM + threadIdx.x] =
        (uint8_t)__nv_cvt_float_to_fp8(v * 512.f, __NV_SATFINITE, __NV_E4M3);
    float s = v * v;
    s = warpReduceSum(s);
    if ((threadIdx.x & 31) == 0) red[threadIdx.x >> 5] = s;
    __syncthreads();
    if (threadIdx.x < 8) {
        float t = red[threadIdx.x];
        #pragma unroll
        for (int o = 4; o > 0; o >>= 1) t += __shfl_down_sync(0xffu, t, o);
        if (threadIdx.x == 0) g_enorm[k] = t;
    }
    if (blockIdx.x == 0 && threadIdx.x < 256) {
        for (int i = threadIdx.x; i < K_CODES; i += 256) g_hist[i] = 0;
    }
}

// ---------------------------------------------------------------------------
// 2) fp8 mma.sync GEMM + best-4/lane + fused exact rescue.
//    CTA: 64 rows x 1024 codes (8 chunks of 128, double-buffered cp.async).
//    8 warps = 4 row-groups x 2 code-halves. grid=512, block=256, 2 CTA/SM.
// ---------------------------------------------------------------------------
__global__ void __launch_bounds__(256, 2)
argmin_fp8_kernel(const float* __restrict__ x, const float* __restrict__ embf) {
    extern __shared__ __align__(16) char smem[];
    float* en_s  = (float*)(smem + SO_EN);
    float* norms = (float*)(smem + SO_NORM);
    int*   flagc = (int*)(smem + SO_FLAG);
    int*   flagr = flagc + 1;

    const int tid  = threadIdx.x;
    const int lane = tid & 31;
    const int w    = tid >> 5;           // 0..7
    const int rg   = w >> 1;             // row group 0..3
    const int chz  = w & 1;              // code half
    const int g4   = lane >> 2;
    const int tg   = lane & 3;
    const int R    = rg << 4;
    const int n0   = blockIdx.x << 6;    // 64 rows per CTA
    const int b    = n0 >> 10;
    const int hw0  = n0 & 1023;
    const float* xb = x + ((size_t)b << 18) + hw0;

    const uint32_t xs_u = smem_u32(smem + SO_XS);
    const uint32_t es_base[2] = { smem_u32(smem + SO_ES0), smem_u32(smem + SO_ES1) };

    // ---- prologue: stage chunk 0 (cp.async, 2048x16B / 256 thr = 8 each)
    #pragma unroll
    for (int it = 0; it < 8; it++) {
        int lin = it * 256 + tid;
        int c   = lin >> 4;
        int sg  = lin & 15;
        CP_ASYNC16(es_base[0] + (uint32_t)(c * XPB + sg * 16),
                   (const void*)(g_e8 + ((size_t)c << 8) + sg * 16));
    }
    CP_COMMIT();
    if (tid == 0) *flagc = 0;

    // ---- pack x tile to e4m3 (row-major) + norm partials (scratch in es1)
    {
        int row = tid & 63;
        int dg  = tid >> 6;              // 0..3 (64 d each)
        const float* p = xb + ((size_t)(dg << 6) << 10) + row;
        float nacc = 0.f;
        uint32_t words[16];
        #pragma unroll
        for (int i = 0; i < 16; i++) {
            float v0 = p[(size_t)(4 * i + 0) << 10];
            float v1 = p[(size_t)(4 * i + 1) << 10];
            float v2 = p[(size_t)(4 * i + 2) << 10];
            float v3 = p[(size_t)(4 * i + 3) << 10];
            nacc = fmaf(v0, v0, nacc); nacc = fmaf(v1, v1, nacc);
            nacc = fmaf(v2, v2, nacc); nacc = fmaf(v3, v3, nacc);
            words[i] = ((uint32_t)pack8x2(v3, v2) << 16) | (uint32_t)pack8x2(v1, v0);
        }
        uint32_t dst = xs_u + (uint32_t)(row * XPB + dg * 64);
        #pragma unroll
        for (int i = 0; i < 4; i++) {
            uint4 u = make_uint4(words[4*i], words[4*i+1], words[4*i+2], words[4*i+3]);
            *(uint4*)(smem + SO_XS + (row * XPB + dg * 64 + 16 * i)) = u;
        }
        (void)dst;
        ((float*)(smem + SO_ES1))[tid] = nacc;
    }
    for (int i = tid; i < K_CODES; i += 256) en_s[i] = g_enorm[i];
    __syncthreads();
    if (tid < 64) {
        const float* sc = (const float*)(smem + SO_ES1);
        norms[tid] = (sc[tid] + sc[tid + 64]) + (sc[tid + 128] + sc[tid + 192]);
    }
    CP_WAIT(0);
    __syncthreads();

    const float na0 = norms[R + g4];
    const float na1 = norms[R + g4 + 8];

    // ldmatrix lane addressing (byte units)
    const int i8  = lane & 7;
    const int sel = lane >> 3;
    const uint32_t a_base = xs_u
        + (uint32_t)((R + i8 + ((sel & 2) ? 8 : 0)) * XPB + ((sel & 1) ? 16 : 0));
    uint32_t b_off[4];
    #pragma unroll
    for (int p = 0; p < 4; p++)
        b_off[p] = (uint32_t)((chz * 64 + p * 16 + i8 + ((sel & 2) ? 8 : 0)) * XPB
                              + ((sel & 1) ? 16 : 0));

    float bva[4], bvb[4]; int bia[4], bib[4];
    #pragma unroll
    for (int j = 0; j < 4; j++) {
        bva[j] = 3.4e38f; bvb[j] = 3.4e38f;
        bia[j] = 0x7fffffff; bib[j] = 0x7fffffff;
    }

    for (int chunk = 0; chunk < 8; chunk++) {
        const uint32_t eb = es_base[chunk & 1];
        if (chunk < 7) {
            #pragma unroll
            for (int it = 0; it < 8; it++) {
                int lin = it * 256 + tid;
                int c   = lin >> 4;
                int sg  = lin & 15;
                CP_ASYNC16(es_base[(chunk + 1) & 1] + (uint32_t)(c * XPB + sg * 16),
                           (const void*)(g_e8 + (((size_t)((chunk + 1) * 128 + c)) << 8) + sg * 16));
            }
            CP_COMMIT();
            CP_WAIT(1);   // current chunk's group retired; next stays in flight
        } else {
            CP_WAIT(0);
        }
        __syncthreads();

        float acc[8][4];
        #pragma unroll
        for (int j = 0; j < 8; j++)
            #pragma unroll
            for (int q = 0; q < 4; q++) acc[j][q] = 0.f;

        #pragma unroll
        for (int K = 0; K < 256; K += 32) {
            uint32_t a0, a1, a2, a3;
            LDM_X4(a0, a1, a2, a3, a_base + (uint32_t)K);
            #pragma unroll
            for (int p = 0; p < 4; p++) {
                uint32_t r0, r1, r2, r3;
                LDM_X4(r0, r1, r2, r3, eb + b_off[p] + (uint32_t)K);
                // A frag order: (rows0-7 k0-15, rows8-15 k0-15, rows0-7 k16-31, rows8-15 k16-31)
                MMA_FP8(acc[2*p][0], acc[2*p][1], acc[2*p][2], acc[2*p][3],
                        a0, a2, a1, a3, r0, r1);
                MMA_FP8(acc[2*p+1][0], acc[2*p+1][1], acc[2*p+1][2], acc[2*p+1][3],
                        a0, a2, a1, a3, r2, r3);
            }
        }
        // epilogue: dist = (a+b) - acc/256 (e scaled x512 -> 2/512)
        const int kb0 = chunk * 128 + chz * 64;
        #pragma unroll
        for (int j = 0; j < 8; j++) {
            int k0 = kb0 + (j >> 1) * 16 + (j & 1) * 8 + 2 * tg;
            float e0 = en_s[k0], e1 = en_s[k0 + 1];
            ins4(fmaf(-0.00390625f, acc[j][0], na0 + e0), k0,     bva, bia);
            ins4(fmaf(-0.00390625f, acc[j][1], na0 + e1), k0 + 1, bva, bia);
            ins4(fmaf(-0.00390625f, acc[j][2], na1 + e0), k0,     bvb, bib);
            ins4(fmaf(-0.00390625f, acc[j][3], na1 + e1), k0 + 1, bvb, bib);
        }
        __syncthreads();
    }

    // ---- candidate staging (alias es region) ----
    float* cand_v = (float*)(smem + SO_ES0);            // [64][32]
    int*   cand_i = (int*)(smem + SO_ES0 + 8192);
    {
        int ra = R + g4, rb = R + g4 + 8;
        int s0 = (chz * 4 + tg) * 4;
        #pragma unroll
        for (int j = 0; j < 4; j++) {
            cand_v[ra * 32 + s0 + j] = bva[j];
            cand_i[ra * 32 + s0 + j] = bia[j];
            cand_v[rb * 32 + s0 + j] = bvb[j];
            cand_i[rb * 32 + s0 + j] = bib[j];
        }
    }
    __syncthreads();

    // ---- decision per row ----
    if (tid < 64) {
        int r = tid;
        float vm = cand_v[r * 32]; int im = cand_i[r * 32];
        #pragma unroll
        for (int j = 1; j < 32; j++) {
            float v = cand_v[r * 32 + j]; int k = cand_i[r * 32 + j];
            if (v < vm || (v == vm && k < im)) { vm = v; im = k; }
        }
        int cnt = 0;
        #pragma unroll
        for (int j = 0; j < 32; j++) cnt += (cand_v[r * 32 + j] <= vm + TAU);
        if (cnt == 1) {
            g_idx[n0 + r] = im;
        } else {
            int slot = atomicAdd(flagc, 1);
            flagr[slot] = r;
        }
    }
    __syncthreads();

    // ---- fused exact rescue: warp per flagged row (exact fp32, ref rounding) ----
    const int nflag = *flagc;
    for (int f = w; f < nflag; f += 8) {
        int r = flagr[f];
        const float* xr = xb + r;
        float xv[8];
        #pragma unroll
        for (int t = 0; t < 8; t++) xv[t] = xr[(size_t)(lane + (t << 5)) << 10];
        float a = norms[r];

        float vmin = cand_v[r * 32];
        #pragma unroll
        for (int j = 1; j < 32; j++) vmin = fminf(vmin, cand_v[r * 32 + j]);

        float bestv = 3.4e38f; int besti = 0x7fffffff;
        for (int j = 0; j < 32; j++) {
            float cv = cand_v[r * 32 + j];
            if (cv > vmin + TAU) continue;
            int k = cand_i[r * 32 + j];
            const float* er = embf + ((size_t)k << 8);
            float d = 0.f;
            #pragma unroll
            for (int t = 0; t < 8; t++) d = fmaf(xv[t], er[lane + (t << 5)], d);
            #pragma unroll
            for (int o = 16; o > 0; o >>= 1) d += __shfl_xor_sync(0xffffffffu, d, o);
            float vv = fmaf(-2.f, d, a + en_s[k]);   // fl(fl(a+b) - 2*dot)
            if (vv < bestv || (vv == bestv && k < besti)) { bestv = vv; besti = k; }
        }
        if (lane == 0) g_idx[n0 + r] = besti;
    }
}

// ---------------------------------------------------------------------------
// 4) Gather (n,d4 mapping) + SSE partials. grid=2048, block=256
// ---------------------------------------------------------------------------
__global__ void gather_kernel(const float* __restrict__ x,
                              const float* __restrict__ emb,
                              float* __restrict__ out) {
    float sse = 0.f;
    const int total = N_TOT * 64;
    for (int T = blockIdx.x * blockDim.x + threadIdx.x; T < total;
         T += gridDim.x * blockDim.x) {
        int n  = T & 32767;
        int d4 = T >> 15;
        int b  = n >> 10;
        int hw = n & 1023;
        int idx = g_idx[n];
        float4 q = *(const float4*)(emb + ((size_t)idx << 8) + (d4 << 2));
        const float* xp = x + ((size_t)b << 18) + ((size_t)(d4 << 2) << 10) + hw;
        float* op = out + ((size_t)b << 18) + ((size_t)(d4 << 2) << 10) + hw;
        float qv[4] = {q.x, q.y, q.z, q.w};
        #pragma unroll
        for (int j = 0; j < 4; j++) {
            float xvj = xp[(size_t)j << 10];
            op[(size_t)j << 10] = qv[j];
            float dd = qv[j] - xvj;
            sse = fmaf(dd, dd, sse);
        }
    }
    __shared__ float red[8];
    sse = warpReduceSum(sse);
    if ((threadIdx.x & 31) == 0) red[threadIdx.x >> 5] = sse;
    __syncthreads();
    if (threadIdx.x < 8) {
        float v = red[threadIdx.x];
        #pragma unroll
        for (int o = 4; o > 0; o >>= 1) v += __shfl_down_sync(0xffu, v, o);
        if (threadIdx.x == 0) g_partials[blockIdx.x] = v;
    }
}

// ---------------------------------------------------------------------------
__global__ void hist_kernel() {
    __shared__ int sh[K_CODES];
    int tid = threadIdx.x;
    for (int i = tid; i < K_CODES; i += 256) sh[i] = 0;
    __syncthreads();
    int base = blockIdx.x * 1024;
    for (int i = tid; i < 1024; i += 256) atomicAdd(&sh[g_idx[base + i]], 1);
    __syncthreads();
    for (int i = tid; i < K_CODES; i += 256)
        if (sh[i]) atomicAdd(&g_hist[i], sh[i]);
}

__global__ void finalize_kernel(float* __restrict__ out, int out_size) {
    __shared__ float red[32];
    int tid = threadIdx.x;
    float s = 0.f;
    for (int i = tid; i < GATHER_BLOCKS; i += 1024) s += g_partials[i];
    s = warpReduceSum(s);
    if ((tid & 31) == 0) red[tid >> 5] = s;
    __syncthreads();
    if (tid < 32) {
        float v = red[tid];
        v = warpReduceSum(v);
        if (tid == 0 && out_size > Q_ELEMS)
            out[Q_ELEMS] = 1.25f * v / (float)Q_ELEMS;
    }
    __syncthreads();
    float p = (float)g_hist[tid] / (float)N_TOT;
    float t = -p * logf(p + 1e-10f);
    t = warpReduceSum(t);
    if ((tid & 31) == 0) red[tid >> 5] = t;
    __syncthreads();
    if (tid < 32) {
        float v = red[tid];
        v = warpReduceSum(v);
        if (tid == 0 && out_size > Q_ELEMS + 1)
            out[Q_ELEMS + 1] = expf(v);
    }
}

__global__ void idx_out_kernel(float* __restrict__ out) {
    int i = blockIdx.x * 256 + threadIdx.x;
    if (i < N_TOT) out[Q_ELEMS + 2 + i] = (float)g_idx[i];
}

// ---------------------------------------------------------------------------
extern "C" void kernel_launch(void* const* d_in, const int* in_sizes, int n_in,
                              void* d_out, int out_size) {
    const float* inputs = (const float*)d_in[0];
    const float* emb    = (const float*)d_in[1];
    if (n_in >= 2 && in_sizes[0] == K_CODES * D_DIM && in_sizes[1] == Q_ELEMS) {
        const float* t = inputs; inputs = emb; emb = t;
    }
    float* out = (float*)d_out;

    cudaFuncSetAttribute(argmin_fp8_kernel,
                         cudaFuncAttributeMaxDynamicSharedMemorySize, SMEM_TOTAL);

    enorm_kernel<<<K_CODES, 256>>>(emb);
    argmin_fp8_kernel<<<N_TOT / 64, 256, SMEM_TOTAL>>>(inputs, emb);
    gather_kernel<<<GATHER_BLOCKS, 256>>>(inputs, emb, out);
    hist_kernel<<<32, 256>>>();
    finalize_kernel<<<1, 1024>>>(out, out_size);
    if (out_size >= Q_ELEMS + 2 + N_TOT) {
        idx_out_kernel<<<128, 256>>>(out);
    }
}

// round 10
// speedup vs baseline: 1.5076x; 1.5076x over previous
#include <cuda_runtime.h>
#include <cuda_bf16.h>
#include <cstdint>

// Problem constants
#define N_TOT   32768
#define D_DIM   256
#define K_CODES 1024
#define Q_ELEMS 8388608
#define TAU     6e-4f

// smem geometry (bytes)
#define XP      136                  // xs pitch in b16
#define EP      264                  // es pitch in b16
#define SO_XS   0                    // 256*136*2 = 69632
#define SO_ES0  69632                // 128*264*2 = 67584
#define SO_ES1  137216
#define SO_EN   204800               // 1024 floats
#define SO_NORM 208896               // 128 floats
#define SO_FLAG 209408               // cnt + 128 ints
#define SO_IDX  209928               // 128 ints
#define SMEM_TOTAL 210440

// Device scratch
__device__ float          g_enorm[K_CODES];
__device__ __nv_bfloat16  g_eb16[K_CODES * D_DIM];
__device__ float          g_partials[256];
__device__ int            g_hist[K_CODES];

__device__ __forceinline__ float warpReduceSum(float v) {
    #pragma unroll
    for (int o = 16; o > 0; o >>= 1) v += __shfl_down_sync(0xffffffffu, v, o);
    return v;
}
__device__ __forceinline__ uint32_t smem_u32(const void* p) {
    uint32_t a;
    asm("{ .reg .u64 t; cvta.to.shared.u64 t, %1; cvt.u32.u64 %0, t; }" : "=r"(a) : "l"(p));
    return a;
}
__device__ __forceinline__ uint32_t packbf(float lo, float hi) {
    return ((uint32_t)__bfloat16_as_ushort(__float2bfloat16(hi)) << 16)
         |  (uint32_t)__bfloat16_as_ushort(__float2bfloat16(lo));
}

#define LDM_X4_T(r0,r1,r2,r3, a)                                               \
    asm volatile("ldmatrix.sync.aligned.m8n8.x4.trans.shared.b16 {%0,%1,%2,%3}, [%4];" \
                 : "=r"(r0), "=r"(r1), "=r"(r2), "=r"(r3) : "r"(a))
#define LDM_X4(r0,r1,r2,r3, a)                                                 \
    asm volatile("ldmatrix.sync.aligned.m8n8.x4.shared.b16 {%0,%1,%2,%3}, [%4];" \
                 : "=r"(r0), "=r"(r1), "=r"(r2), "=r"(r3) : "r"(a))
#define MMA_BF16(c0,c1,c2,c3, a0,a1,a2,a3, b0,b1)                              \
    asm volatile("mma.sync.aligned.m16n8k16.row.col.f32.bf16.bf16.f32 "        \
                 "{%0,%1,%2,%3},{%4,%5,%6,%7},{%8,%9},{%0,%1,%2,%3};"          \
                 : "+f"(c0), "+f"(c1), "+f"(c2), "+f"(c3)                      \
                 : "r"(a0), "r"(a1), "r"(a2), "r"(a3), "r"(b0), "r"(b1))
#define CP_ASYNC16(dst, src)                                                   \
    asm volatile("cp.async.cg.shared.global [%0], [%1], 16;" :: "r"(dst), "l"(src))
#define CP_COMMIT() asm volatile("cp.async.commit_group;" ::: "memory")
#define CP_WAIT(n)  asm volatile("cp.async.wait_group %0;" :: "n"(n) : "memory")

__device__ __forceinline__ void ins3(float v, int k, float bv[3], int bi[3]) {
    if (v < bv[2] || (v == bv[2] && k < bi[2])) {
        bv[2] = v; bi[2] = k;
        #pragma unroll
        for (int t = 2; t > 0; t--) {
            if (bv[t] < bv[t-1] || (bv[t] == bv[t-1] && bi[t] < bi[t-1])) {
                float tv = bv[t]; bv[t] = bv[t-1]; bv[t-1] = tv;
                int   ti = bi[t]; bi[t] = bi[t-1]; bi[t-1] = ti;
            }
        }
    }
}

// ---------------------------------------------------------------------------
// 1) prep: ||e_k||^2 + e->bf16 + zero hist. grid=1024, block=256
// ---------------------------------------------------------------------------
__global__ void prep_kernel(const float* __restrict__ emb) {
    __shared__ float red[8];
    int k = blockIdx.x;
    float v = emb[k * D_DIM + threadIdx.x];
    g_eb16[k * D_DIM + threadIdx.x] = __float2bfloat16(v);
    float s = v * v;
    s = warpReduceSum(s);
    if ((threadIdx.x & 31) == 0) red[threadIdx.x >> 5] = s;
    __syncthreads();
    if (threadIdx.x < 8) {
        float t = red[threadIdx.x];
        #pragma unroll
        for (int o = 4; o > 0; o >>= 1) t += __shfl_down_sync(0xffu, t, o);
        if (threadIdx.x == 0) g_enorm[k] = t;
    }
    if (blockIdx.x == 0) {
        for (int i = threadIdx.x; i < K_CODES; i += 256) g_hist[i] = 0;
    }
}

// ---------------------------------------------------------------------------
// 2) bf16 mma.sync GEMM + best-3/lane + fused exact rescue
//    + fused gather/SSE/hist/idx-out.
//    CTA: 128 rows x 1024 codes (8 chunks of 128, double-buffered cp.async).
//    16 warps = 8 row-groups x 2 code-halves. grid=256, block=512.
// ---------------------------------------------------------------------------
__global__ void __launch_bounds__(512, 1)
argmin_bf16_kernel(const float* __restrict__ x, const float* __restrict__ embf,
                   float* __restrict__ out, int out_size) {
    extern __shared__ __align__(16) char smem[];
    __nv_bfloat16* xs = (__nv_bfloat16*)(smem + SO_XS);
    float* en_s  = (float*)(smem + SO_EN);
    float* norms = (float*)(smem + SO_NORM);
    int*   flagc = (int*)(smem + SO_FLAG);
    int*   flagr = flagc + 1;
    int*   idx_s = (int*)(smem + SO_IDX);

    const int tid  = threadIdx.x;
    const int lane = tid & 31;
    const int w    = tid >> 5;           // 0..15
    const int rg   = w >> 1;             // row group 0..7
    const int chz  = w & 1;              // code half 0..1
    const int g4   = lane >> 2;
    const int tg   = lane & 3;
    const int R    = rg << 4;
    const int n0   = blockIdx.x << 7;
    const int b    = n0 >> 10;
    const int hw0  = n0 & 1023;
    const float* xb = x + ((size_t)b << 18) + hw0;

    const uint32_t es_base[2] = { smem_u32(smem + SO_ES0), smem_u32(smem + SO_ES1) };

    // ---- prologue: kick off chunk 0 staging via cp.async
    #pragma unroll
    for (int it = 0; it < 8; it++) {
        int lin = it * 512 + tid;        // 0..4095
        int c   = lin >> 5;
        int d8  = (lin & 31) << 3;
        CP_ASYNC16(es_base[0] + (uint32_t)(c * (EP * 2) + d8 * 2),
                   (const void*)(g_eb16 + ((size_t)c << 8) + d8));
    }
    CP_COMMIT();
    if (tid == 0) *flagc = 0;

    // ---- fill xs (bf16) ----
    #pragma unroll
    for (int i = 0; i < 8; i++) {
        int lin = i * 512 + tid;
        int d   = lin >> 4;
        int r8  = (lin & 15) << 3;
        float4 t0 = *(const float4*)(xb + ((size_t)d << 10) + r8);
        float4 t1 = *(const float4*)(xb + ((size_t)d << 10) + r8 + 4);
        uint4 u;
        u.x = packbf(t0.x, t0.y); u.y = packbf(t0.z, t0.w);
        u.z = packbf(t1.x, t1.y); u.w = packbf(t1.z, t1.w);
        *(uint4*)&xs[d * XP + r8] = u;
    }
    // ---- exact fp32 row norms: quarter-row per thread, scratch in es1
    {
        int row = tid & 127;
        int qd  = tid >> 7;              // 0..3
        float a = 0.f;
        const float* p = xb + ((size_t)(qd << 6) << 10) + row;
        #pragma unroll 8
        for (int d = 0; d < 64; d++) a = fmaf(p[(size_t)d << 10], p[(size_t)d << 10], a);
        ((float*)(smem + SO_ES1))[tid] = a;
    }
    for (int i = tid; i < K_CODES; i += 512) en_s[i] = g_enorm[i];
    __syncthreads();
    if (tid < 128) {
        const float* sc = (const float*)(smem + SO_ES1);
        norms[tid] = ((sc[tid] + sc[tid + 128]) + (sc[tid + 256] + sc[tid + 384]));
    }
    CP_WAIT(0);
    __syncthreads();

    const float na0 = norms[R + g4];
    const float na1 = norms[R + g4 + 8];

    // per-lane ldmatrix addressing
    const uint32_t xs_u = smem_u32(xs);
    const int i8  = lane & 7;
    const int sel = lane >> 3;
    const uint32_t a_base = xs_u
        + (uint32_t)(((i8 + ((sel & 2) ? 8 : 0)) * XP + R + ((sel & 1) ? 8 : 0)) * 2);
    uint32_t b_off[4];
    #pragma unroll
    for (int p = 0; p < 4; p++)
        b_off[p] = (uint32_t)(((chz * 64 + p * 16 + i8 + ((sel & 2) ? 8 : 0)) * EP) * 2
                              + ((sel & 1) ? 16 : 0));

    float bva[3], bvb[3]; int bia[3], bib[3];
    #pragma unroll
    for (int j = 0; j < 3; j++) {
        bva[j] = 3.4e38f; bvb[j] = 3.4e38f;
        bia[j] = 0x7fffffff; bib[j] = 0x7fffffff;
    }

    for (int chunk = 0; chunk < 8; chunk++) {
        const uint32_t eb = es_base[chunk & 1];
        if (chunk < 7) {   // stage next chunk
            #pragma unroll
            for (int it = 0; it < 8; it++) {
                int lin = it * 512 + tid;
                int c   = lin >> 5;
                int d8  = (lin & 31) << 3;
                CP_ASYNC16(es_base[(chunk + 1) & 1] + (uint32_t)(c * (EP * 2) + d8 * 2),
                           (const void*)(g_eb16 + (((size_t)((chunk + 1) * 128 + c)) << 8) + d8));
            }
            CP_COMMIT();
        }

        float acc[8][4];
        #pragma unroll
        for (int j = 0; j < 8; j++)
            #pragma unroll
            for (int q = 0; q < 4; q++) acc[j][q] = 0.f;

        #pragma unroll
        for (int K = 0; K < 256; K += 16) {
            uint32_t a0, a1, a2, a3;
            LDM_X4_T(a0, a1, a2, a3, a_base + (uint32_t)(K * XP * 2));
            #pragma unroll
            for (int p = 0; p < 4; p++) {
                uint32_t r0, r1, r2, r3;
                LDM_X4(r0, r1, r2, r3, eb + b_off[p] + (uint32_t)(K * 2));
                MMA_BF16(acc[2*p][0], acc[2*p][1], acc[2*p][2], acc[2*p][3],
                         a0, a1, a2, a3, r0, r1);
                MMA_BF16(acc[2*p+1][0], acc[2*p+1][1], acc[2*p+1][2], acc[2*p+1][3],
                         a0, a1, a2, a3, r2, r3);
            }
        }
        // epilogue: dist + best-3 insert
        const int kb0 = chunk * 128 + chz * 64;
        #pragma unroll
        for (int j = 0; j < 8; j++) {
            int k0 = kb0 + (j >> 1) * 16 + (j & 1) * 8 + 2 * tg;
            float e0 = en_s[k0], e1 = en_s[k0 + 1];
            ins3(fmaf(-2.f, acc[j][0], na0 + e0), k0,     bva, bia);
            ins3(fmaf(-2.f, acc[j][1], na0 + e1), k0 + 1, bva, bia);
            ins3(fmaf(-2.f, acc[j][2], na1 + e0), k0,     bvb, bib);
            ins3(fmaf(-2.f, acc[j][3], na1 + e1), k0 + 1, bvb, bib);
        }
        if (chunk < 7) CP_WAIT(1);
        __syncthreads();
    }

    // ---- candidate staging (alias es0; all MMA reads done) ----
    float* cand_v = (float*)(smem + SO_ES0);             // [128][24]
    int*   cand_i = (int*)(smem + SO_ES0 + 12288);
    {
        int ra = R + g4, rb = R + g4 + 8;
        int s0 = (chz * 4 + tg) * 3;
        #pragma unroll
        for (int j = 0; j < 3; j++) {
            cand_v[ra * 24 + s0 + j] = bva[j];
            cand_i[ra * 24 + s0 + j] = bia[j];
            cand_v[rb * 24 + s0 + j] = bvb[j];
            cand_i[rb * 24 + s0 + j] = bib[j];
        }
    }
    __syncthreads();

    // ---- decision per row ----
    if (tid < 128) {
        int r = tid;
        float vm = cand_v[r * 24]; int im = cand_i[r * 24];
        #pragma unroll
        for (int j = 1; j < 24; j++) {
            float v = cand_v[r * 24 + j]; int k = cand_i[r * 24 + j];
            if (v < vm || (v == vm && k < im)) { vm = v; im = k; }
        }
        int cnt = 0;
        #pragma unroll
        for (int j = 0; j < 24; j++) cnt += (cand_v[r * 24 + j] <= vm + TAU);
        if (cnt == 1) {
            idx_s[r] = im;
        } else {
            int slot = atomicAdd(flagc, 1);
            flagr[slot] = r;
        }
    }
    __syncthreads();

    // ---- fused exact rescue: warp per flagged row ----
    const int nflag = *flagc;
    for (int f = w; f < nflag; f += 16) {
        int r = flagr[f];
        const float* xr = xb + r;
        float xv[8];
        #pragma unroll
        for (int t = 0; t < 8; t++) xv[t] = xr[(size_t)(lane + (t << 5)) << 10];
        float a = norms[r];   // exact fp32 (translation-invariant vs reference)

        float vmin = cand_v[r * 24];
        #pragma unroll
        for (int j = 1; j < 24; j++) vmin = fminf(vmin, cand_v[r * 24 + j]);

        float bestv = 3.4e38f; int besti = 0x7fffffff;
        for (int j = 0; j < 24; j++) {
            float cv = cand_v[r * 24 + j];
            if (cv > vmin + TAU) continue;
            int k = cand_i[r * 24 + j];
            const float* er = embf + ((size_t)k << 8);
            float d = 0.f;
            #pragma unroll
            for (int t = 0; t < 8; t++) d = fmaf(xv[t], er[lane + (t << 5)], d);
            #pragma unroll
            for (int o = 16; o > 0; o >>= 1) d += __shfl_xor_sync(0xffffffffu, d, o);
            float vv = fmaf(-2.f, d, a + en_s[k]);   // fl(fl(a+b) - 2*dot)
            if (vv < bestv || (vv == bestv && k < besti)) { bestv = vv; besti = k; }
        }
        if (lane == 0) idx_s[r] = besti;
    }
    __syncthreads();

    // ---- fused hist + index writeout ----
    if (tid < 128) {
        int idx = idx_s[tid];
        atomicAdd(&g_hist[idx], 1);
        if (out_size >= Q_ELEMS + 2 + N_TOT)
            out[Q_ELEMS + 2 + n0 + tid] = (float)idx;
    }

    // ---- fused gather + SSE for this CTA's 128 rows ----
    float sse = 0.f;
    #pragma unroll
    for (int u = 0; u < 16; u++) {
        int lin = u * 512 + tid;          // 0..8191
        int r   = lin & 127;
        int d4  = lin >> 7;               // 0..63
        int idx = idx_s[r];
        float4 q = *(const float4*)(embf + ((size_t)idx << 8) + (d4 << 2));
        const float* xp = xb + ((size_t)(d4 << 2) << 10) + r;
        float* op = out + ((size_t)b << 18) + ((size_t)(d4 << 2) << 10) + hw0 + r;
        float qv[4] = {q.x, q.y, q.z, q.w};
        #pragma unroll
        for (int j = 0; j < 4; j++) {
            float xvj = xp[(size_t)j << 10];
            op[(size_t)j << 10] = qv[j];
            float dd = qv[j] - xvj;
            sse = fmaf(dd, dd, sse);
        }
    }
    {
        __shared__ float red[16];
        sse = warpReduceSum(sse);
        if (lane == 0) red[w] = sse;
        __syncthreads();
        if (tid < 16) {
            float v = red[tid];
            #pragma unroll
            for (int o = 8; o > 0; o >>= 1) v += __shfl_down_sync(0xffffu, v, o);
            if (tid == 0) g_partials[blockIdx.x] = v;
        }
    }
}

// ---------------------------------------------------------------------------
// 3) finalize: loss + perplexity. grid=1, block=1024
// ---------------------------------------------------------------------------
__global__ void finalize_kernel(float* __restrict__ out, int out_size) {
    __shared__ float red[32];
    int tid = threadIdx.x;
    float s = (tid < 256) ? g_partials[tid] : 0.f;
    s = warpReduceSum(s);
    if ((tid & 31) == 0) red[tid >> 5] = s;
    __syncthreads();
    if (tid < 32) {
        float v = red[tid];
        v = warpReduceSum(v);
        if (tid == 0 && out_size > Q_ELEMS)
            out[Q_ELEMS] = 1.25f * v / (float)Q_ELEMS;   // q_latent + 0.25*e_latent
    }
    __syncthreads();
    float p = (float)g_hist[tid] / (float)N_TOT;
    float t = -p * logf(p + 1e-10f);
    t = warpReduceSum(t);
    if ((tid & 31) == 0) red[tid >> 5] = t;
    __syncthreads();
    if (tid < 32) {
        float v = red[tid];
        v = warpReduceSum(v);
        if (tid == 0 && out_size > Q_ELEMS + 1)
            out[Q_ELEMS + 1] = expf(v);
    }
}

// ---------------------------------------------------------------------------
extern "C" void kernel_launch(void* const* d_in, const int* in_sizes, int n_in,
                              void* d_out, int out_size) {
    const float* inputs = (const float*)d_in[0];
    const float* emb    = (const float*)d_in[1];
    if (n_in >= 2 && in_sizes[0] == K_CODES * D_DIM && in_sizes[1] == Q_ELEMS) {
        const float* t = inputs; inputs = emb; emb = t;
    }
    float* out = (float*)d_out;

    cudaFuncSetAttribute(argmin_bf16_kernel,
                         cudaFuncAttributeMaxDynamicSharedMemorySize, SMEM_TOTAL);

    prep_kernel<<<K_CODES, 256>>>(emb);
    argmin_bf16_kernel<<<N_TOT / 128, 512, SMEM_TOTAL>>>(inputs, emb, out, out_size);
    finalize_kernel<<<1, 1024>>>(out, out_size);
}